// round 16
// baseline (speedup 1.0000x reference)
#include <cuda_runtime.h>
#include <cstdint>

// Fused single-kernel two-reduction over 8M points:
//   g   = sum_i exp(-0.5*((|p_i - cam|-2)/4)^2) / (4*sqrt(2*pi))
//   cnt = # points strictly inside rotated+translated CCW triangle
// out[0] = 1/(g+eps) + 1/(cnt+eps)
// Count = N - (# outside) via sign-bit OR of the three crosses.
// Loads: ld.global.cg (L2-only, no L1 allocation) — zero reuse stream,
// so skip L1 fill work on the L1tex path where the bottleneck sits.

#define GRID    608          // 4 CTAs/SM * 152 SMs, one exact wave
#define THREADS 256
#define UNROLL  8

__device__ float g_partial_gauss[GRID];
__device__ float g_partial_out[GRID];
__device__ int   g_ticket = 0;   // reset by finalizing block each call

#define GAUSS_NORM 0.09973557010f   // 1 / (4 * sqrt(2*pi))
#define EPSV 1e-06f
// exp(-0.5*((d-2)/4)^2) = ex2(-(K*d - 2K)^2), K = sqrt(0.5*log2(e))/4
#define KFOLD  0.2123346587f
#define KFOLD2 0.4246693174f        // 2*K

__device__ __forceinline__ float fast_sqrt(float x) {
    float r; asm("sqrt.approx.f32 %0, %1;" : "=f"(r) : "f"(x)); return r;
}
__device__ __forceinline__ float fast_ex2(float x) {
    float r; asm("ex2.approx.f32 %0, %1;" : "=f"(r) : "f"(x)); return r;
}
// L2-only load: no L1 allocation for this zero-reuse stream
__device__ __forceinline__ float4 ldg_cg(const float4* p) {
    float4 q;
    asm("ld.global.cg.v4.f32 {%0,%1,%2,%3}, [%4];"
        : "=f"(q.x), "=f"(q.y), "=f"(q.z), "=f"(q.w) : "l"(p));
    return q;
}

struct Geo {
    float cx, cy;
    float a0, b0, d0, a1, b1, d1, a2, b2, d2;  // cross_k(p) = a*px + b*py + d
};

__device__ __forceinline__ void body(const float px, const float py,
                                     const Geo& G, float& acc_g, int& acc_out)
{
    // gaussian
    float dx = px - G.cx, dy = py - G.cy;
    float d  = fast_sqrt(fmaf(dx, dx, dy * dy));
    float w  = fmaf(d, KFOLD, -KFOLD2);          // K*(d-2)
    acc_g += fast_ex2(w * -w);                   // ex2(-(K(d-2))^2)

    // CCW triangle => inside <=> all crosses > 0; count OUTSIDE via sign bits
    float c0 = fmaf(G.a0, px, fmaf(G.b0, py, G.d0));
    float c1 = fmaf(G.a1, px, fmaf(G.b1, py, G.d1));
    float c2 = fmaf(G.a2, px, fmaf(G.b2, py, G.d2));
    uint32_t u = __float_as_uint(c0) | __float_as_uint(c1) | __float_as_uint(c2);
    acc_out += (int)(u >> 31);
}

__global__ __launch_bounds__(THREADS, 4)
void fused_kernel(const float4* __restrict__ pts4, int n4,
                  const float* __restrict__ cam, int odd_point,
                  const float* __restrict__ pts_scalar,
                  float n_points,
                  float* __restrict__ out)
{
    // ---- uniform geometry setup ----
    Geo G;
    G.cx = cam[0]; G.cy = cam[1];
    const float yaw = cam[2];
    float s, c;
    __sincosf(yaw, &s, &c);
    // POLY {(0,0),(2,7),(-2,7)} is CCW; rotation preserves orientation,
    // so all-negative is impossible (c0+c1+c2 = 2*area > 0).
    const float v0x = G.cx,                      v0y = G.cy;
    const float v1x =  2.f*c - 7.f*s + G.cx,     v1y =  2.f*s + 7.f*c + G.cy;
    const float v2x = -2.f*c - 7.f*s + G.cx,     v2y = -2.f*s + 7.f*c + G.cy;
    {
        float ex = v1x - v0x, ey = v1y - v0y;
        G.a0 = -ey; G.b0 = ex; G.d0 = ey * v0x - ex * v0y;
        ex = v2x - v1x; ey = v2y - v1y;
        G.a1 = -ey; G.b1 = ex; G.d1 = ey * v1x - ex * v1y;
        ex = v0x - v2x; ey = v0y - v2y;
        G.a2 = -ey; G.b2 = ex; G.d2 = ey * v2x - ex * v2y;
    }

    float acc_g0 = 0.f, acc_g1 = 0.f;
    int   acc_out = 0;

    const int stride  = GRID * THREADS;
    const int tid0    = blockIdx.x * THREADS + threadIdx.x;
    const int strideU = UNROLL * stride;

    int i = tid0;
    for (; i + (UNROLL - 1) * stride < n4; i += strideU) {
        float4 q[UNROLL];
        #pragma unroll
        for (int u = 0; u < UNROLL; u++) q[u] = ldg_cg(pts4 + i + u * stride);
        #pragma unroll
        for (int u = 0; u < UNROLL; u++) {
            body(q[u].x, q[u].y, G, acc_g0, acc_out);
            body(q[u].z, q[u].w, G, acc_g1, acc_out);
        }
    }
    for (; i < n4; i += stride) {
        float4 q = ldg_cg(pts4 + i);
        body(q.x, q.y, G, acc_g0, acc_out);
        body(q.z, q.w, G, acc_g1, acc_out);
    }
    // lone trailing point if N odd
    if (odd_point && blockIdx.x == 0 && threadIdx.x == 0) {
        body(pts_scalar[4 * n4], pts_scalar[4 * n4 + 1], G, acc_g0, acc_out);
    }

    float acc_g = (acc_g0 + acc_g1) * GAUSS_NORM;
    float acc_o = (float)acc_out;

    // ---- block reduction (fixed tree -> deterministic) ----
    __shared__ float sg[THREADS];
    __shared__ float so[THREADS];
    sg[threadIdx.x] = acc_g;
    so[threadIdx.x] = acc_o;
    __syncthreads();
    #pragma unroll
    for (int off = THREADS / 2; off > 0; off >>= 1) {
        if (threadIdx.x < off) {
            sg[threadIdx.x] += sg[threadIdx.x + off];
            so[threadIdx.x] += so[threadIdx.x + off];
        }
        __syncthreads();
    }

    __shared__ bool is_last;
    if (threadIdx.x == 0) {
        g_partial_gauss[blockIdx.x] = sg[0];
        g_partial_out[blockIdx.x]   = so[0];
        __threadfence();
        is_last = (atomicAdd(&g_ticket, 1) == GRID - 1);
    }
    __syncthreads();

    if (is_last) {
        __threadfence();
        float ag = 0.f, ao = 0.f;
        for (int k = threadIdx.x; k < GRID; k += THREADS) {
            ag += g_partial_gauss[k];
            ao += g_partial_out[k];
        }
        sg[threadIdx.x] = ag;
        so[threadIdx.x] = ao;
        __syncthreads();
        #pragma unroll
        for (int off = THREADS / 2; off > 0; off >>= 1) {
            if (threadIdx.x < off) {
                sg[threadIdx.x] += sg[threadIdx.x + off];
                so[threadIdx.x] += so[threadIdx.x + off];
            }
            __syncthreads();
        }
        if (threadIdx.x == 0) {
            float inside = n_points - so[0];
            out[0] = 1.0f / (sg[0] + EPSV) + 1.0f / (inside + EPSV);
            g_ticket = 0;   // re-arm for graph replay
        }
    }
}

extern "C" void kernel_launch(void* const* d_in, const int* in_sizes, int n_in,
                              void* d_out, int out_size)
{
    const float* points = (const float*)d_in[0];   // [N,2] float32
    const float* cam    = (const float*)d_in[1];   // [3]  float32
    float* out = (float*)d_out;

    int n_floats  = in_sizes[0];          // 2*N
    int n4        = n_floats / 4;         // float4 groups (2 points each)
    int odd_point = ((n_floats / 2) & 1); // lone trailing point if N odd
    float n_points = (float)(n_floats / 2);

    fused_kernel<<<GRID, THREADS>>>((const float4*)points, n4, cam,
                                    odd_point, points, n_points, out);
}